// round 1
// baseline (speedup 1.0000x reference)
#include <cuda_runtime.h>
#include <math.h>

#define BATCH   4
#define CH      512
#define HWSZ    4096
#define NGROUPS 32
#define CPG     (CH / NGROUPS)      // 16
#define GSIZE   (CPG * HWSZ)        // 65536

// ---------------- scratch (static device globals; no allocs allowed) --------
__device__ float g_h[(size_t)BATCH * CH * HWSZ];        // 32 MB
__device__ float g_q[(size_t)BATCH * CH * HWSZ];        // 32 MB
__device__ float g_k[(size_t)BATCH * CH * HWSZ];        // 32 MB
__device__ float g_v[(size_t)BATCH * CH * HWSZ];        // 32 MB
__device__ float g_attn[(size_t)BATCH * HWSZ * HWSZ];   // 256 MB

// ---------------- GroupNorm --------------------------------------------------
// One block per (batch, group). Two passes over the 64K-element group
// (second pass hits L2). Stats via E[x^2]-mu^2 (x~N(0,1): no cancellation risk).
__global__ void groupnorm_kernel(const float* __restrict__ x,
                                 const float* __restrict__ gw,
                                 const float* __restrict__ gb) {
    const int bg  = blockIdx.x;
    const int b   = bg / NGROUPS;
    const int grp = bg % NGROUPS;
    const size_t base = ((size_t)b * CH + (size_t)grp * CPG) * HWSZ;
    const float4* xp = (const float4*)(x + base);
    const int n4 = GSIZE / 4;

    float sum = 0.f, sq = 0.f;
    for (int i = threadIdx.x; i < n4; i += blockDim.x) {
        float4 v = xp[i];
        sum += v.x + v.y + v.z + v.w;
        sq  += v.x * v.x + v.y * v.y + v.z * v.z + v.w * v.w;
    }
    __shared__ float sbuf[64];
    #pragma unroll
    for (int o = 16; o; o >>= 1) {
        sum += __shfl_xor_sync(0xffffffffu, sum, o);
        sq  += __shfl_xor_sync(0xffffffffu, sq,  o);
    }
    const int wid = threadIdx.x >> 5, lid = threadIdx.x & 31;
    const int nw  = blockDim.x >> 5;
    if (lid == 0) { sbuf[wid] = sum; sbuf[32 + wid] = sq; }
    __syncthreads();
    if (threadIdx.x < 32) {
        sum = (lid < nw) ? sbuf[lid]      : 0.f;
        sq  = (lid < nw) ? sbuf[32 + lid] : 0.f;
        #pragma unroll
        for (int o = 16; o; o >>= 1) {
            sum += __shfl_xor_sync(0xffffffffu, sum, o);
            sq  += __shfl_xor_sync(0xffffffffu, sq,  o);
        }
        if (lid == 0) { sbuf[0] = sum; sbuf[1] = sq; }
    }
    __syncthreads();
    const float mu   = sbuf[0] * (1.f / GSIZE);
    const float var  = sbuf[1] * (1.f / GSIZE) - mu * mu;
    const float rstd = rsqrtf(var + 1e-6f);

    float4* hp = (float4*)(g_h + base);
    for (int i = threadIdx.x; i < n4; i += blockDim.x) {
        const int ch = grp * CPG + (i * 4) / HWSZ;   // float4 never crosses a channel row
        const float sc = gw[ch] * rstd;
        const float sh = gb[ch] - mu * sc;
        float4 v = xp[i];
        float4 r;
        r.x = v.x * sc + sh; r.y = v.y * sc + sh;
        r.z = v.z * sc + sh; r.w = v.w * sc + sh;
        hp[i] = r;
    }
}

// ---------------- generic SGEMM ---------------------------------------------
// C[m,n] = alpha * sum_k A(m,k) * B(k,n)  (+ bias[m]) (+ resid[m,n])
//   TA=false: A[m*lda + k]    TA=true: A[k*lda + m]
//   TB=false: B[k*ldb + n]    TB=true: B[n*ldb + k]
// blockIdx.z = batch (strides sA/sB/sC/sR). All dims divide BM/BN/BK exactly.
#define BM 128
#define BN 128
#define BKK 16
#define TM 8
#define TN 8
#define AST (BM + 4)
#define BST (BN + 4)

template<bool TA, bool TB>
__global__ void __launch_bounds__(256)
sgemm_kernel(const float* __restrict__ A, const float* __restrict__ Bm,
             float* __restrict__ Cm,
             int K, int lda, int ldb, int ldc,
             long long sA, long long sB, long long sC,
             float alpha, const float* __restrict__ bias,
             const float* __restrict__ resid, long long sR)
{
    __shared__ float As[BKK][AST];
    __shared__ float Bs[BKK][BST];

    const int bz = blockIdx.z;
    A  += (size_t)bz * sA;
    Bm += (size_t)bz * sB;
    Cm += (size_t)bz * sC;
    if (resid) resid += (size_t)bz * sR;

    const int m0 = blockIdx.y * BM, n0 = blockIdx.x * BN;
    const int t  = threadIdx.x;
    const int tx = t & 15, ty = t >> 4;

    float acc[TM][TN];
    #pragma unroll
    for (int i = 0; i < TM; i++)
        #pragma unroll
        for (int j = 0; j < TN; j++) acc[i][j] = 0.f;

    for (int k0 = 0; k0 < K; k0 += BKK) {
        #pragma unroll
        for (int i = 0; i < 8; i++) {
            const int l = i * 256 + t;
            if (TA) { const int k = l / BM, m = l % BM;
                      As[k][m] = A[(size_t)(k0 + k) * lda + m0 + m]; }
            else    { const int m = l / BKK, k = l % BKK;
                      As[k][m] = A[(size_t)(m0 + m) * lda + k0 + k]; }
        }
        #pragma unroll
        for (int i = 0; i < 8; i++) {
            const int l = i * 256 + t;
            if (!TB) { const int k = l / BN, n = l % BN;
                       Bs[k][n] = Bm[(size_t)(k0 + k) * ldb + n0 + n]; }
            else     { const int n = l / BKK, k = l % BKK;
                       Bs[k][n] = Bm[(size_t)(n0 + n) * ldb + k0 + k]; }
        }
        __syncthreads();
        #pragma unroll
        for (int kk = 0; kk < BKK; kk++) {
            float af[TM], bf[TN];
            #pragma unroll
            for (int i = 0; i < TM; i++) af[i] = As[kk][ty * TM + i];
            #pragma unroll
            for (int j = 0; j < TN; j++) bf[j] = Bs[kk][tx * TN + j];
            #pragma unroll
            for (int i = 0; i < TM; i++)
                #pragma unroll
                for (int j = 0; j < TN; j++) acc[i][j] += af[i] * bf[j];
        }
        __syncthreads();
    }

    #pragma unroll
    for (int i = 0; i < TM; i++) {
        const int m = m0 + ty * TM + i;
        const float bv = bias ? bias[m] : 0.f;
        #pragma unroll
        for (int j = 0; j < TN; j++) {
            const int n = n0 + tx * TN + j;
            float v = acc[i][j] * alpha + bv;
            if (resid) v += resid[(size_t)m * ldc + n];
            Cm[(size_t)m * ldc + n] = v;
        }
    }
}

// ---------------- row softmax over g_attn ------------------------------------
// One block (256 thr) per row of 4096; 16 values/thread stay in registers.
__global__ void softmax_kernel() {
    const size_t row = blockIdx.x;
    float4* p = (float4*)(g_attn + row * HWSZ);
    float4 v[4];
    float mx = -1e30f;
    #pragma unroll
    for (int i = 0; i < 4; i++) {
        v[i] = p[threadIdx.x + i * 256];
        mx = fmaxf(mx, fmaxf(fmaxf(v[i].x, v[i].y), fmaxf(v[i].z, v[i].w)));
    }
    __shared__ float sb[32];
    #pragma unroll
    for (int o = 16; o; o >>= 1) mx = fmaxf(mx, __shfl_xor_sync(0xffffffffu, mx, o));
    const int wid = threadIdx.x >> 5, lid = threadIdx.x & 31;
    if (lid == 0) sb[wid] = mx;
    __syncthreads();
    if (threadIdx.x < 32) {
        mx = (lid < 8) ? sb[lid] : -1e30f;
        #pragma unroll
        for (int o = 4; o; o >>= 1) mx = fmaxf(mx, __shfl_xor_sync(0xffffffffu, mx, o));
        if (lid == 0) sb[0] = mx;
    }
    __syncthreads();
    mx = sb[0];

    float sum = 0.f;
    #pragma unroll
    for (int i = 0; i < 4; i++) {
        v[i].x = __expf(v[i].x - mx); v[i].y = __expf(v[i].y - mx);
        v[i].z = __expf(v[i].z - mx); v[i].w = __expf(v[i].w - mx);
        sum += v[i].x + v[i].y + v[i].z + v[i].w;
    }
    __syncthreads();
    #pragma unroll
    for (int o = 16; o; o >>= 1) sum += __shfl_xor_sync(0xffffffffu, sum, o);
    if (lid == 0) sb[wid] = sum;
    __syncthreads();
    if (threadIdx.x < 32) {
        sum = (lid < 8) ? sb[lid] : 0.f;
        #pragma unroll
        for (int o = 4; o; o >>= 1) sum += __shfl_xor_sync(0xffffffffu, sum, o);
        if (lid == 0) sb[0] = sum;
    }
    __syncthreads();
    const float inv = 1.f / sb[0];
    #pragma unroll
    for (int i = 0; i < 4; i++) {
        v[i].x *= inv; v[i].y *= inv; v[i].z *= inv; v[i].w *= inv;
        p[threadIdx.x + i * 256] = v[i];
    }
}

// ---------------- launch ------------------------------------------------------
extern "C" void kernel_launch(void* const* d_in, const int* in_sizes, int n_in,
                              void* d_out, int out_size) {
    const float* x    = (const float*)d_in[0];
    const float* gn_w = (const float*)d_in[1];
    const float* gn_b = (const float*)d_in[2];
    const float* q_w  = (const float*)d_in[3];
    const float* q_b  = (const float*)d_in[4];
    const float* k_w  = (const float*)d_in[5];
    const float* k_b  = (const float*)d_in[6];
    const float* v_w  = (const float*)d_in[7];
    const float* v_b  = (const float*)d_in[8];
    float* out = (float*)d_out;

    void *hp, *qp, *kp, *vp, *ap;
    cudaGetSymbolAddress(&hp, g_h);
    cudaGetSymbolAddress(&qp, g_q);
    cudaGetSymbolAddress(&kp, g_k);
    cudaGetSymbolAddress(&vp, g_v);
    cudaGetSymbolAddress(&ap, g_attn);
    float* h_ptr = (float*)hp;
    float* q_ptr = (float*)qp;
    float* k_ptr = (float*)kp;
    float* v_ptr = (float*)vp;
    float* a_ptr = (float*)ap;

    const long long sCHW = (long long)CH * HWSZ;
    const long long sAtt = (long long)HWSZ * HWSZ;

    // 1) GroupNorm: x -> g_h
    groupnorm_kernel<<<BATCH * NGROUPS, 512>>>(x, gn_w, gn_b);

    // 2) QKV 1x1 convs: W[512x512] @ h[512x4096] + bias, per batch
    dim3 g1(HWSZ / BN, CH / BM, BATCH);   // (32, 4, 4)
    sgemm_kernel<false, false><<<g1, 256>>>(q_w, h_ptr, q_ptr,
        CH, CH, HWSZ, HWSZ, 0, sCHW, sCHW, 1.f, q_b, nullptr, 0);
    sgemm_kernel<false, false><<<g1, 256>>>(k_w, h_ptr, k_ptr,
        CH, CH, HWSZ, HWSZ, 0, sCHW, sCHW, 1.f, k_b, nullptr, 0);
    sgemm_kernel<false, false><<<g1, 256>>>(v_w, h_ptr, v_ptr,
        CH, CH, HWSZ, HWSZ, 0, sCHW, sCHW, 1.f, v_b, nullptr, 0);

    // 3) S = (1/sqrt(C)) * Q^T K : M=N=4096, K=512
    dim3 g2(HWSZ / BN, HWSZ / BM, BATCH); // (32, 32, 4)
    const float alpha = 1.f / sqrtf((float)CH);
    sgemm_kernel<true, false><<<g2, 256>>>(q_ptr, k_ptr, a_ptr,
        CH, HWSZ, HWSZ, HWSZ, sCHW, sCHW, sAtt, alpha, nullptr, nullptr, 0);

    // 4) softmax over last dim, in place
    softmax_kernel<<<BATCH * HWSZ, 256>>>();

    // 5) out = x + V @ P^T : M=512(c), N=4096(i), K=4096(j)
    dim3 g3(HWSZ / BN, CH / BM, BATCH);   // (32, 4, 4)
    sgemm_kernel<false, true><<<g3, 256>>>(v_ptr, a_ptr, out,
        HWSZ, HWSZ, HWSZ, HWSZ, sCHW, sAtt, sCHW, 1.f, nullptr, x, sCHW);
}

// round 2
// speedup vs baseline: 3.7166x; 3.7166x over previous
#include <cuda_runtime.h>
#include <math.h>
#include <stdint.h>

#define BATCH   4
#define CH      512
#define HWSZ    4096
#define NGROUPS 32
#define CPG     16
#define GSIZE   (CPG * HWSZ)

// ---------------- scratch ----------------------------------------------------
__device__ float g_ht[(size_t)BATCH * HWSZ * CH];     // h^T  [b][hw][c]
__device__ float g_qt[(size_t)BATCH * HWSZ * CH];     // q^T  [b][hw][c]
__device__ float g_kt[(size_t)BATCH * HWSZ * CH];     // k^T  [b][hw][c]
__device__ float g_v [(size_t)BATCH * CH * HWSZ];     // v    [b][c][hw]
__device__ float g_attn[(size_t)BATCH * HWSZ * HWSZ]; // attn [b][i][j]

// ---------------- GroupNorm (writes h^T) -------------------------------------
__global__ void groupnorm_kernel(const float* __restrict__ x,
                                 const float* __restrict__ gw,
                                 const float* __restrict__ gb) {
    const int bg  = blockIdx.x;
    const int b   = bg / NGROUPS;
    const int grp = bg % NGROUPS;
    const size_t base = ((size_t)b * CH + (size_t)grp * CPG) * HWSZ;
    const float4* xp = (const float4*)(x + base);
    const int n4 = GSIZE / 4;

    float sum = 0.f, sq = 0.f;
    for (int i = threadIdx.x; i < n4; i += blockDim.x) {
        float4 v = xp[i];
        sum += v.x + v.y + v.z + v.w;
        sq  += v.x * v.x + v.y * v.y + v.z * v.z + v.w * v.w;
    }
    __shared__ float sbuf[64];
    #pragma unroll
    for (int o = 16; o; o >>= 1) {
        sum += __shfl_xor_sync(0xffffffffu, sum, o);
        sq  += __shfl_xor_sync(0xffffffffu, sq,  o);
    }
    const int wid = threadIdx.x >> 5, lid = threadIdx.x & 31;
    const int nw  = blockDim.x >> 5;
    if (lid == 0) { sbuf[wid] = sum; sbuf[32 + wid] = sq; }
    __syncthreads();
    if (threadIdx.x < 32) {
        sum = (lid < nw) ? sbuf[lid]      : 0.f;
        sq  = (lid < nw) ? sbuf[32 + lid] : 0.f;
        #pragma unroll
        for (int o = 16; o; o >>= 1) {
            sum += __shfl_xor_sync(0xffffffffu, sum, o);
            sq  += __shfl_xor_sync(0xffffffffu, sq,  o);
        }
        if (lid == 0) { sbuf[0] = sum; sbuf[1] = sq; }
    }
    __syncthreads();
    const float mu   = sbuf[0] * (1.f / GSIZE);
    const float var  = sbuf[1] * (1.f / GSIZE) - mu * mu;
    const float rstd = rsqrtf(var + 1e-6f);

    __shared__ float s_sc[CPG], s_sh[CPG];
    if (threadIdx.x < CPG) {
        const int c = grp * CPG + threadIdx.x;
        const float sc = gw[c] * rstd;
        s_sc[threadIdx.x] = sc;
        s_sh[threadIdx.x] = gb[c] - mu * sc;
    }
    __syncthreads();

    // write transposed: ht[b][pos][grp*16 + c_local], float4 along c
    const float* xb = x + base;
    float* ho = g_ht + (size_t)b * HWSZ * CH + grp * CPG;
    for (int idx = threadIdx.x; idx < HWSZ * 4; idx += blockDim.x) {
        const int pos = idx >> 2;
        const int j   = (idx & 3) * 4;
        float4 r;
        r.x = xb[(size_t)(j + 0) * HWSZ + pos] * s_sc[j + 0] + s_sh[j + 0];
        r.y = xb[(size_t)(j + 1) * HWSZ + pos] * s_sc[j + 1] + s_sh[j + 1];
        r.z = xb[(size_t)(j + 2) * HWSZ + pos] * s_sc[j + 2] + s_sh[j + 2];
        r.w = xb[(size_t)(j + 3) * HWSZ + pos] * s_sc[j + 3] + s_sh[j + 3];
        *(float4*)(ho + (size_t)pos * CH + j) = r;
    }
}

// ---------------- TF32 MMA GEMM:  C[m][n] = alpha*sum_k A[m][k]*B[n][k] ------
// A row-major [M,K] (lda), B row-major [N,K] (ldb).
// STORET: C stored transposed C[n*ldc + m]; else C[m*ldc + n] (+bias[m], +resid)
#define BM  128
#define BN  128
#define BK  32
#define KST 36   // stride%32==4 -> frag-load bank = 4g+q : conflict-free

__device__ __forceinline__ uint32_t f2tf(float x) {
    uint32_t r; asm("cvt.rna.tf32.f32 %0, %1;" : "=r"(r) : "f"(x)); return r;
}

template<bool STORET, bool HASBIAS, bool HASRES>
__global__ void __launch_bounds__(256)
mma_gemm(const float* __restrict__ A, const float* __restrict__ B,
         float* __restrict__ C, int K, int lda, int ldb, int ldc,
         long long sA, long long sB, long long sC, long long sR,
         float alpha, const float* __restrict__ bias,
         const float* __restrict__ resid)
{
    __shared__ uint32_t As[BM * KST];
    __shared__ uint32_t Bs[BN * KST];

    const int bz = blockIdx.z;
    A += (size_t)bz * sA;
    B += (size_t)bz * sB;
    C += (size_t)bz * sC;
    const float* R = HASRES ? (resid + (size_t)bz * sR) : nullptr;

    const int m0 = blockIdx.y * BM, n0 = blockIdx.x * BN;
    const int t = threadIdx.x, lane = t & 31, warp = t >> 5;
    const int wm = (warp >> 2) * 64, wn = (warp & 3) * 32;
    const int g = lane >> 2, q = lane & 3;

    // global->smem mapping: thread covers rows rb+32i, k-chunk kv (float4)
    const int rb = t >> 3, kv = t & 7;
    const float* Ag = A + (size_t)(m0 + rb) * lda + kv * 4;
    const float* Bg = B + (size_t)(n0 + rb) * ldb + kv * 4;

    float4 pa[4], pb[4];
    #pragma unroll
    for (int i = 0; i < 4; i++) pa[i] = *(const float4*)(Ag + (size_t)i * 32 * lda);
    #pragma unroll
    for (int i = 0; i < 4; i++) pb[i] = *(const float4*)(Bg + (size_t)i * 32 * ldb);

    float acc[4][4][4];
    #pragma unroll
    for (int mt = 0; mt < 4; mt++)
        #pragma unroll
        for (int nt = 0; nt < 4; nt++)
            #pragma unroll
            for (int r = 0; r < 4; r++) acc[mt][nt][r] = 0.f;

    for (int k0 = 0; k0 < K; k0 += BK) {
        #pragma unroll
        for (int i = 0; i < 4; i++) {
            uint4 u;
            u.x = f2tf(pa[i].x); u.y = f2tf(pa[i].y);
            u.z = f2tf(pa[i].z); u.w = f2tf(pa[i].w);
            *(uint4*)&As[(i * 32 + rb) * KST + kv * 4] = u;
        }
        #pragma unroll
        for (int i = 0; i < 4; i++) {
            uint4 u;
            u.x = f2tf(pb[i].x); u.y = f2tf(pb[i].y);
            u.z = f2tf(pb[i].z); u.w = f2tf(pb[i].w);
            *(uint4*)&Bs[(i * 32 + rb) * KST + kv * 4] = u;
        }
        __syncthreads();

        if (k0 + BK < K) {
            Ag += BK; Bg += BK;
            #pragma unroll
            for (int i = 0; i < 4; i++) pa[i] = *(const float4*)(Ag + (size_t)i * 32 * lda);
            #pragma unroll
            for (int i = 0; i < 4; i++) pb[i] = *(const float4*)(Bg + (size_t)i * 32 * ldb);
        }

        #pragma unroll
        for (int kk = 0; kk < BK; kk += 8) {
            uint32_t af[4][4], bf[4][2];
            #pragma unroll
            for (int mt = 0; mt < 4; mt++) {
                const uint32_t* p = &As[(wm + mt * 16 + g) * KST + kk + q];
                af[mt][0] = p[0];
                af[mt][1] = p[8 * KST];
                af[mt][2] = p[4];
                af[mt][3] = p[8 * KST + 4];
            }
            #pragma unroll
            for (int nt = 0; nt < 4; nt++) {
                const uint32_t* p = &Bs[(wn + nt * 8 + g) * KST + kk + q];
                bf[nt][0] = p[0];
                bf[nt][1] = p[4];
            }
            #pragma unroll
            for (int mt = 0; mt < 4; mt++)
                #pragma unroll
                for (int nt = 0; nt < 4; nt++) {
                    asm volatile(
                        "mma.sync.aligned.m16n8k8.row.col.f32.tf32.tf32.f32 "
                        "{%0,%1,%2,%3}, {%4,%5,%6,%7}, {%8,%9}, {%0,%1,%2,%3};"
                        : "+f"(acc[mt][nt][0]), "+f"(acc[mt][nt][1]),
                          "+f"(acc[mt][nt][2]), "+f"(acc[mt][nt][3])
                        : "r"(af[mt][0]), "r"(af[mt][1]), "r"(af[mt][2]), "r"(af[mt][3]),
                          "r"(bf[nt][0]), "r"(bf[nt][1]));
                }
        }
        __syncthreads();
    }

    // epilogue
    #pragma unroll
    for (int mt = 0; mt < 4; mt++) {
        const int m = m0 + wm + mt * 16 + g;
        const float bv0 = HASBIAS ? bias[m]     : 0.f;
        const float bv1 = HASBIAS ? bias[m + 8] : 0.f;
        #pragma unroll
        for (int nt = 0; nt < 4; nt++) {
            const int n = n0 + wn + nt * 8 + 2 * q;
            float c0 = acc[mt][nt][0] * alpha + bv0;
            float c1 = acc[mt][nt][1] * alpha + bv0;
            float c2 = acc[mt][nt][2] * alpha + bv1;
            float c3 = acc[mt][nt][3] * alpha + bv1;
            if (STORET) {
                C[(size_t)n       * ldc + m]     = c0;
                C[(size_t)(n + 1) * ldc + m]     = c1;
                C[(size_t)n       * ldc + m + 8] = c2;
                C[(size_t)(n + 1) * ldc + m + 8] = c3;
            } else {
                if (HASRES) {
                    c0 += R[(size_t)m       * ldc + n];
                    c1 += R[(size_t)m       * ldc + n + 1];
                    c2 += R[(size_t)(m + 8) * ldc + n];
                    c3 += R[(size_t)(m + 8) * ldc + n + 1];
                }
                float2 v01 = make_float2(c0, c1);
                float2 v23 = make_float2(c2, c3);
                *(float2*)&C[(size_t)m       * ldc + n] = v01;
                *(float2*)&C[(size_t)(m + 8) * ldc + n] = v23;
            }
        }
    }
}

// ---------------- row softmax over g_attn ------------------------------------
__global__ void softmax_kernel() {
    const size_t row = blockIdx.x;
    float4* p = (float4*)(g_attn + row * HWSZ);
    float4 v[4];
    float mx = -1e30f;
    #pragma unroll
    for (int i = 0; i < 4; i++) {
        v[i] = p[threadIdx.x + i * 256];
        mx = fmaxf(mx, fmaxf(fmaxf(v[i].x, v[i].y), fmaxf(v[i].z, v[i].w)));
    }
    __shared__ float sb[32];
    #pragma unroll
    for (int o = 16; o; o >>= 1) mx = fmaxf(mx, __shfl_xor_sync(0xffffffffu, mx, o));
    const int wid = threadIdx.x >> 5, lid = threadIdx.x & 31;
    if (lid == 0) sb[wid] = mx;
    __syncthreads();
    if (threadIdx.x < 32) {
        mx = (lid < 8) ? sb[lid] : -1e30f;
        #pragma unroll
        for (int o = 4; o; o >>= 1) mx = fmaxf(mx, __shfl_xor_sync(0xffffffffu, mx, o));
        if (lid == 0) sb[0] = mx;
    }
    __syncthreads();
    mx = sb[0];

    float sum = 0.f;
    #pragma unroll
    for (int i = 0; i < 4; i++) {
        v[i].x = __expf(v[i].x - mx); v[i].y = __expf(v[i].y - mx);
        v[i].z = __expf(v[i].z - mx); v[i].w = __expf(v[i].w - mx);
        sum += v[i].x + v[i].y + v[i].z + v[i].w;
    }
    __syncthreads();
    #pragma unroll
    for (int o = 16; o; o >>= 1) sum += __shfl_xor_sync(0xffffffffu, sum, o);
    if (lid == 0) sb[wid] = sum;
    __syncthreads();
    if (threadIdx.x < 32) {
        sum = (lid < 8) ? sb[lid] : 0.f;
        #pragma unroll
        for (int o = 4; o; o >>= 1) sum += __shfl_xor_sync(0xffffffffu, sum, o);
        if (lid == 0) sb[0] = sum;
    }
    __syncthreads();
    const float inv = 1.f / sb[0];
    #pragma unroll
    for (int i = 0; i < 4; i++) {
        v[i].x *= inv; v[i].y *= inv; v[i].z *= inv; v[i].w *= inv;
        p[threadIdx.x + i * 256] = v[i];
    }
}

// ---------------- launch ------------------------------------------------------
extern "C" void kernel_launch(void* const* d_in, const int* in_sizes, int n_in,
                              void* d_out, int out_size) {
    const float* x    = (const float*)d_in[0];
    const float* gn_w = (const float*)d_in[1];
    const float* gn_b = (const float*)d_in[2];
    const float* q_w  = (const float*)d_in[3];
    const float* q_b  = (const float*)d_in[4];
    const float* k_w  = (const float*)d_in[5];
    const float* k_b  = (const float*)d_in[6];
    const float* v_w  = (const float*)d_in[7];
    const float* v_b  = (const float*)d_in[8];
    float* out = (float*)d_out;

    void *htp, *qtp, *ktp, *vp, *ap;
    cudaGetSymbolAddress(&htp, g_ht);
    cudaGetSymbolAddress(&qtp, g_qt);
    cudaGetSymbolAddress(&ktp, g_kt);
    cudaGetSymbolAddress(&vp,  g_v);
    cudaGetSymbolAddress(&ap,  g_attn);
    float* ht_ptr = (float*)htp;
    float* qt_ptr = (float*)qtp;
    float* kt_ptr = (float*)ktp;
    float* v_ptr  = (float*)vp;
    float* a_ptr  = (float*)ap;

    const long long sHC  = (long long)HWSZ * CH;
    const long long sCHW = (long long)CH * HWSZ;
    const long long sAtt = (long long)HWSZ * HWSZ;

    // 1) GroupNorm: x -> h^T
    groupnorm_kernel<<<BATCH * NGROUPS, 512>>>(x, gn_w, gn_b);

    // 2) QKV:  C[o][hw] = sum_c W[o][c] * ht[hw][c]   (M=512, N=4096, K=512)
    dim3 g1(HWSZ / BN, CH / BM, BATCH);
    // q, k stored transposed [hw][c]; v stored natural [c][hw]
    mma_gemm<true,  true, false><<<g1, 256>>>(q_w, ht_ptr, qt_ptr, CH, CH, CH, CH,
        0, sHC, sHC, 0, 1.f, q_b, nullptr);
    mma_gemm<true,  true, false><<<g1, 256>>>(k_w, ht_ptr, kt_ptr, CH, CH, CH, CH,
        0, sHC, sHC, 0, 1.f, k_b, nullptr);
    mma_gemm<false, true, false><<<g1, 256>>>(v_w, ht_ptr, v_ptr, CH, CH, CH, HWSZ,
        0, sHC, sCHW, 0, 1.f, v_b, nullptr);

    // 3) S[i][j] = (1/sqrt(C)) sum_c qt[i][c] kt[j][c]   (M=N=4096, K=512)
    dim3 g2(HWSZ / BN, HWSZ / BM, BATCH);
    const float alpha = 1.f / sqrtf((float)CH);
    mma_gemm<false, false, false><<<g2, 256>>>(qt_ptr, kt_ptr, a_ptr, CH, CH, CH, HWSZ,
        sHC, sHC, sAtt, 0, alpha, nullptr, nullptr);

    // 4) softmax rows of attn
    softmax_kernel<<<BATCH * HWSZ, 256>>>();

    // 5) out[c][i] = x[c][i] + sum_j v[c][j] attn[i][j]  (M=512, N=4096, K=4096)
    dim3 g3(HWSZ / BN, CH / BM, BATCH);
    mma_gemm<false, false, true><<<g3, 256>>>(v_ptr, a_ptr, out, HWSZ, HWSZ, HWSZ, HWSZ,
        sCHW, sAtt, sCHW, sCHW, 1.f, nullptr, x);
}

// round 3
// speedup vs baseline: 5.9875x; 1.6110x over previous
#include <cuda_runtime.h>
#include <cuda_bf16.h>
#include <math.h>
#include <stdint.h>

#define BATCH   4
#define CH      512
#define HWSZ    4096
#define NGROUPS 32
#define CPG     16
#define GSIZE   (CPG * HWSZ)

// ---------------- scratch (bf16 intermediates) -------------------------------
__device__ __nv_bfloat16 g_wq[CH * CH];
__device__ __nv_bfloat16 g_wk[CH * CH];
__device__ __nv_bfloat16 g_wv[CH * CH];
__device__ __nv_bfloat16 g_ht[(size_t)BATCH * HWSZ * CH];     // h^T [b][hw][c]
__device__ __nv_bfloat16 g_qt[(size_t)BATCH * HWSZ * CH];     // q^T [b][hw][c]
__device__ __nv_bfloat16 g_kt[(size_t)BATCH * HWSZ * CH];     // k^T [b][hw][c]
__device__ __nv_bfloat16 g_v [(size_t)BATCH * CH * HWSZ];     // v   [b][c][hw]
__device__ __nv_bfloat16 g_attn[(size_t)BATCH * HWSZ * HWSZ]; // attn [b][i][j]

// ---------------- weight fp32 -> bf16 ---------------------------------------
__global__ void convw_kernel(const float* __restrict__ qw,
                             const float* __restrict__ kw,
                             const float* __restrict__ vw) {
    const int i = blockIdx.x * blockDim.x + threadIdx.x;   // 0..65535 (x4 elems)
    float4 a;
    a = ((const float4*)qw)[i];
    ((__nv_bfloat162*)g_wq)[2 * i]     = __floats2bfloat162_rn(a.x, a.y);
    ((__nv_bfloat162*)g_wq)[2 * i + 1] = __floats2bfloat162_rn(a.z, a.w);
    a = ((const float4*)kw)[i];
    ((__nv_bfloat162*)g_wk)[2 * i]     = __floats2bfloat162_rn(a.x, a.y);
    ((__nv_bfloat162*)g_wk)[2 * i + 1] = __floats2bfloat162_rn(a.z, a.w);
    a = ((const float4*)vw)[i];
    ((__nv_bfloat162*)g_wv)[2 * i]     = __floats2bfloat162_rn(a.x, a.y);
    ((__nv_bfloat162*)g_wv)[2 * i + 1] = __floats2bfloat162_rn(a.z, a.w);
}

// ---------------- GroupNorm (fp32 stats, writes bf16 h^T) --------------------
__global__ void groupnorm_kernel(const float* __restrict__ x,
                                 const float* __restrict__ gw,
                                 const float* __restrict__ gb) {
    const int bg  = blockIdx.x;
    const int b   = bg / NGROUPS;
    const int grp = bg % NGROUPS;
    const size_t base = ((size_t)b * CH + (size_t)grp * CPG) * HWSZ;
    const float4* xp = (const float4*)(x + base);
    const int n4 = GSIZE / 4;

    float sum = 0.f, sq = 0.f;
    for (int i = threadIdx.x; i < n4; i += blockDim.x) {
        float4 v = xp[i];
        sum += v.x + v.y + v.z + v.w;
        sq  += v.x * v.x + v.y * v.y + v.z * v.z + v.w * v.w;
    }
    __shared__ float sbuf[64];
    #pragma unroll
    for (int o = 16; o; o >>= 1) {
        sum += __shfl_xor_sync(0xffffffffu, sum, o);
        sq  += __shfl_xor_sync(0xffffffffu, sq,  o);
    }
    const int wid = threadIdx.x >> 5, lid = threadIdx.x & 31;
    const int nw  = blockDim.x >> 5;
    if (lid == 0) { sbuf[wid] = sum; sbuf[32 + wid] = sq; }
    __syncthreads();
    if (threadIdx.x < 32) {
        sum = (lid < nw) ? sbuf[lid]      : 0.f;
        sq  = (lid < nw) ? sbuf[32 + lid] : 0.f;
        #pragma unroll
        for (int o = 16; o; o >>= 1) {
            sum += __shfl_xor_sync(0xffffffffu, sum, o);
            sq  += __shfl_xor_sync(0xffffffffu, sq,  o);
        }
        if (lid == 0) { sbuf[0] = sum; sbuf[1] = sq; }
    }
    __syncthreads();
    const float mu   = sbuf[0] * (1.f / GSIZE);
    const float var  = sbuf[1] * (1.f / GSIZE) - mu * mu;
    const float rstd = rsqrtf(var + 1e-6f);

    __shared__ float s_sc[CPG], s_sh[CPG];
    if (threadIdx.x < CPG) {
        const int c = grp * CPG + threadIdx.x;
        const float sc = gw[c] * rstd;
        s_sc[threadIdx.x] = sc;
        s_sh[threadIdx.x] = gb[c] - mu * sc;
    }
    __syncthreads();

    // write h^T[b][pos][grp*16 + j], 8 channels per thread-iter (16B store)
    const float* xb = x + base;
    __nv_bfloat16* ho = g_ht + (size_t)b * HWSZ * CH + grp * CPG;
    for (int idx = threadIdx.x; idx < HWSZ * 2; idx += blockDim.x) {
        const int pos = idx >> 1;
        const int jh  = (idx & 1) * 8;
        __nv_bfloat162 r[4];
        #pragma unroll
        for (int r2 = 0; r2 < 4; r2++) {
            const int j = jh + r2 * 2;
            float v0 = xb[(size_t)j       * HWSZ + pos] * s_sc[j]     + s_sh[j];
            float v1 = xb[(size_t)(j + 1) * HWSZ + pos] * s_sc[j + 1] + s_sh[j + 1];
            r[r2] = __floats2bfloat162_rn(v0, v1);
        }
        *(uint4*)(ho + (size_t)pos * CH + jh) = *(uint4*)r;
    }
}

// ---------------- bf16 MMA GEMM:  C[m][n] = alpha*sum_k A[m][k]*B[n][k] ------
// A row-major [M,K] (lda elems), B row-major [N,K] (ldb). Both bf16.
// 2-stage cp.async pipeline, m16n8k16 bf16 mma, fp32 accumulate.
#define BM  128
#define BN  128
#define BK  32
#define RST 40   // smem row stride in bf16 elems (32 data + 8 pad): conflict-free

__device__ __forceinline__ void cp16(uint32_t s, const void* g) {
    asm volatile("cp.async.cg.shared.global [%0], [%1], 16;\n" :: "r"(s), "l"(g));
}

template<bool STORET, bool HASBIAS, bool HASRES, bool OUTBF16>
__global__ void __launch_bounds__(256)
bgemm(const __nv_bfloat16* __restrict__ A, const __nv_bfloat16* __restrict__ B,
      void* __restrict__ Cv, int K, int lda, int ldb, int ldc,
      long long strA, long long strB, long long strC, long long strR,
      float alpha, const float* __restrict__ bias,
      const float* __restrict__ resid)
{
    __shared__ __nv_bfloat16 smA[2][BM * RST];
    __shared__ __nv_bfloat16 smB[2][BN * RST];

    const int bz = blockIdx.z;
    A += (size_t)bz * strA;
    B += (size_t)bz * strB;
    const float* R = HASRES ? (resid + (size_t)bz * strR) : nullptr;

    const int m0 = blockIdx.y * BM, n0 = blockIdx.x * BN;
    const int t = threadIdx.x, lane = t & 31, warp = t >> 5;
    const int wm = (warp >> 2) * 64, wn = (warp & 3) * 32;
    const int g = lane >> 2, q = lane & 3;

    // loader mapping: thread -> rows (t>>2, t>>2 + 64), 16B chunk (t&3)
    const int lrow = t >> 2, lchk = t & 3;
    const __nv_bfloat16* Ag = A + (size_t)(m0 + lrow) * lda + lchk * 8;
    const __nv_bfloat16* Bg = B + (size_t)(n0 + lrow) * ldb + lchk * 8;
    const uint32_t saB = (uint32_t)__cvta_generic_to_shared(&smA[0][0])
                       + (lrow * RST + lchk * 8) * 2;
    const uint32_t sbB = (uint32_t)__cvta_generic_to_shared(&smB[0][0])
                       + (lrow * RST + lchk * 8) * 2;

    const int ntiles = K / BK;

    // prologue: stage 0
    {
        cp16(saB,                 Ag);
        cp16(saB + 64 * RST * 2,  Ag + (size_t)64 * lda);
        cp16(sbB,                 Bg);
        cp16(sbB + 64 * RST * 2,  Bg + (size_t)64 * ldb);
        asm volatile("cp.async.commit_group;\n");
    }

    float acc[4][4][4];
    #pragma unroll
    for (int mt = 0; mt < 4; mt++)
        #pragma unroll
        for (int nt = 0; nt < 4; nt++)
            #pragma unroll
            for (int r = 0; r < 4; r++) acc[mt][nt][r] = 0.f;

    for (int kt = 0; kt < ntiles; kt++) {
        if (kt + 1 < ntiles) {
            const int s = (kt + 1) & 1;
            const __nv_bfloat16* ag = Ag + (size_t)(kt + 1) * BK;
            const __nv_bfloat16* bg = Bg + (size_t)(kt + 1) * BK;
            const uint32_t sa = saB + s * (BM * RST * 2);
            const uint32_t sb = sbB + s * (BN * RST * 2);
            cp16(sa,                ag);
            cp16(sa + 64 * RST * 2, ag + (size_t)64 * lda);
            cp16(sb,                bg);
            cp16(sb + 64 * RST * 2, bg + (size_t)64 * ldb);
        }
        asm volatile("cp.async.commit_group;\n");
        asm volatile("cp.async.wait_group 1;\n");
        __syncthreads();

        const __nv_bfloat16* As = smA[kt & 1];
        const __nv_bfloat16* Bs = smB[kt & 1];

        #pragma unroll
        for (int kk = 0; kk < BK; kk += 16) {
            uint32_t af[4][4], bf[4][2];
            #pragma unroll
            for (int mt = 0; mt < 4; mt++) {
                const __nv_bfloat16* p = As + (wm + mt * 16 + g) * RST + kk + 2 * q;
                af[mt][0] = *(const uint32_t*)(p);
                af[mt][1] = *(const uint32_t*)(p + 8 * RST);
                af[mt][2] = *(const uint32_t*)(p + 8);
                af[mt][3] = *(const uint32_t*)(p + 8 * RST + 8);
            }
            #pragma unroll
            for (int nt = 0; nt < 4; nt++) {
                const __nv_bfloat16* p = Bs + (wn + nt * 8 + g) * RST + kk + 2 * q;
                bf[nt][0] = *(const uint32_t*)(p);
                bf[nt][1] = *(const uint32_t*)(p + 8);
            }
            #pragma unroll
            for (int mt = 0; mt < 4; mt++)
                #pragma unroll
                for (int nt = 0; nt < 4; nt++) {
                    asm volatile(
                        "mma.sync.aligned.m16n8k16.row.col.f32.bf16.bf16.f32 "
                        "{%0,%1,%2,%3}, {%4,%5,%6,%7}, {%8,%9}, {%0,%1,%2,%3};"
                        : "+f"(acc[mt][nt][0]), "+f"(acc[mt][nt][1]),
                          "+f"(acc[mt][nt][2]), "+f"(acc[mt][nt][3])
                        : "r"(af[mt][0]), "r"(af[mt][1]), "r"(af[mt][2]), "r"(af[mt][3]),
                          "r"(bf[nt][0]), "r"(bf[nt][1]));
                }
        }
        __syncthreads();
    }

    // epilogue: c0:(m,n) c1:(m,n+1) c2:(m+8,n) c3:(m+8,n+1)
    #pragma unroll
    for (int mt = 0; mt < 4; mt++) {
        const int m = m0 + wm + mt * 16 + g;
        const float bv0 = HASBIAS ? bias[m]     : 0.f;
        const float bv1 = HASBIAS ? bias[m + 8] : 0.f;
        #pragma unroll
        for (int nt = 0; nt < 4; nt++) {
            const int n = n0 + wn + nt * 8 + 2 * q;
            float c0 = acc[mt][nt][0] * alpha + bv0;
            float c1 = acc[mt][nt][1] * alpha + bv0;
            float c2 = acc[mt][nt][2] * alpha + bv1;
            float c3 = acc[mt][nt][3] * alpha + bv1;
            if (OUTBF16) {
                __nv_bfloat16* C = (__nv_bfloat16*)Cv + (size_t)bz * strC;
                if (STORET) {
                    C[(size_t)n       * ldc + m]     = __float2bfloat16_rn(c0);
                    C[(size_t)(n + 1) * ldc + m]     = __float2bfloat16_rn(c1);
                    C[(size_t)n       * ldc + m + 8] = __float2bfloat16_rn(c2);
                    C[(size_t)(n + 1) * ldc + m + 8] = __float2bfloat16_rn(c3);
                } else {
                    *(__nv_bfloat162*)&C[(size_t)m       * ldc + n] =
                        __floats2bfloat162_rn(c0, c1);
                    *(__nv_bfloat162*)&C[(size_t)(m + 8) * ldc + n] =
                        __floats2bfloat162_rn(c2, c3);
                }
            } else {
                float* C = (float*)Cv + (size_t)bz * strC;
                if (HASRES) {
                    c0 += R[(size_t)m       * ldc + n];
                    c1 += R[(size_t)m       * ldc + n + 1];
                    c2 += R[(size_t)(m + 8) * ldc + n];
                    c3 += R[(size_t)(m + 8) * ldc + n + 1];
                }
                *(float2*)&C[(size_t)m       * ldc + n] = make_float2(c0, c1);
                *(float2*)&C[(size_t)(m + 8) * ldc + n] = make_float2(c2, c3);
            }
        }
    }
}

// ---------------- row softmax over bf16 g_attn (fp32 math) -------------------
__global__ void softmax_kernel() {
    const size_t row = blockIdx.x;
    uint4* p = (uint4*)(g_attn + row * HWSZ);   // 8 bf16 per uint4
    uint4 u[2];
    float f[16];
    u[0] = p[threadIdx.x];
    u[1] = p[threadIdx.x + 256];
    #pragma unroll
    for (int i = 0; i < 2; i++) {
        const uint32_t* w = (const uint32_t*)&u[i];
        #pragma unroll
        for (int j = 0; j < 4; j++) {
            float2 v = __bfloat1622float2(*(const __nv_bfloat162*)&w[j]);
            f[i * 8 + j * 2]     = v.x;
            f[i * 8 + j * 2 + 1] = v.y;
        }
    }
    float mx = -1e30f;
    #pragma unroll
    for (int i = 0; i < 16; i++) mx = fmaxf(mx, f[i]);
    __shared__ float sb[32];
    #pragma unroll
    for (int o = 16; o; o >>= 1) mx = fmaxf(mx, __shfl_xor_sync(0xffffffffu, mx, o));
    const int wid = threadIdx.x >> 5, lid = threadIdx.x & 31;
    if (lid == 0) sb[wid] = mx;
    __syncthreads();
    if (threadIdx.x < 32) {
        mx = (lid < 8) ? sb[lid] : -1e30f;
        #pragma unroll
        for (int o = 4; o; o >>= 1) mx = fmaxf(mx, __shfl_xor_sync(0xffffffffu, mx, o));
        if (lid == 0) sb[0] = mx;
    }
    __syncthreads();
    mx = sb[0];

    float sum = 0.f;
    #pragma unroll
    for (int i = 0; i < 16; i++) { f[i] = __expf(f[i] - mx); sum += f[i]; }
    __syncthreads();
    #pragma unroll
    for (int o = 16; o; o >>= 1) sum += __shfl_xor_sync(0xffffffffu, sum, o);
    if (lid == 0) sb[wid] = sum;
    __syncthreads();
    if (threadIdx.x < 32) {
        sum = (lid < 8) ? sb[lid] : 0.f;
        #pragma unroll
        for (int o = 4; o; o >>= 1) sum += __shfl_xor_sync(0xffffffffu, sum, o);
        if (lid == 0) sb[0] = sum;
    }
    __syncthreads();
    const float inv = 1.f / sb[0];
    #pragma unroll
    for (int i = 0; i < 2; i++) {
        uint32_t* w = (uint32_t*)&u[i];
        #pragma unroll
        for (int j = 0; j < 4; j++) {
            __nv_bfloat162 b2 = __floats2bfloat162_rn(f[i * 8 + j * 2] * inv,
                                                      f[i * 8 + j * 2 + 1] * inv);
            w[j] = *(uint32_t*)&b2;
        }
    }
    p[threadIdx.x]       = u[0];
    p[threadIdx.x + 256] = u[1];
}

// ---------------- launch ------------------------------------------------------
extern "C" void kernel_launch(void* const* d_in, const int* in_sizes, int n_in,
                              void* d_out, int out_size) {
    const float* x    = (const float*)d_in[0];
    const float* gn_w = (const float*)d_in[1];
    const float* gn_b = (const float*)d_in[2];
    const float* q_w  = (const float*)d_in[3];
    const float* q_b  = (const float*)d_in[4];
    const float* k_w  = (const float*)d_in[5];
    const float* k_b  = (const float*)d_in[6];
    const float* v_w  = (const float*)d_in[7];
    const float* v_b  = (const float*)d_in[8];
    float* out = (float*)d_out;

    void *wqp, *wkp, *wvp, *htp, *qtp, *ktp, *vp, *ap;
    cudaGetSymbolAddress(&wqp, g_wq);
    cudaGetSymbolAddress(&wkp, g_wk);
    cudaGetSymbolAddress(&wvp, g_wv);
    cudaGetSymbolAddress(&htp, g_ht);
    cudaGetSymbolAddress(&qtp, g_qt);
    cudaGetSymbolAddress(&ktp, g_kt);
    cudaGetSymbolAddress(&vp,  g_v);
    cudaGetSymbolAddress(&ap,  g_attn);
    __nv_bfloat16* wq = (__nv_bfloat16*)wqp;
    __nv_bfloat16* wk = (__nv_bfloat16*)wkp;
    __nv_bfloat16* wv = (__nv_bfloat16*)wvp;
    __nv_bfloat16* ht = (__nv_bfloat16*)htp;
    __nv_bfloat16* qt = (__nv_bfloat16*)qtp;
    __nv_bfloat16* kt = (__nv_bfloat16*)ktp;
    __nv_bfloat16* vv = (__nv_bfloat16*)vp;
    __nv_bfloat16* at = (__nv_bfloat16*)ap;

    const long long sHC  = (long long)HWSZ * CH;
    const long long sCHW = (long long)CH * HWSZ;
    const long long sAtt = (long long)HWSZ * HWSZ;

    // 0) weights -> bf16
    convw_kernel<<<CH * CH / 4 / 256, 256>>>(q_w, k_w, v_w);

    // 1) GroupNorm: x -> bf16 h^T
    groupnorm_kernel<<<BATCH * NGROUPS, 512>>>(x, gn_w, gn_b);

    // 2) QKV: C[o][hw] = sum_c W[o][c] ht[hw][c]  (M=512, N=4096, K=512)
    dim3 g1(HWSZ / BN, CH / BM, BATCH);
    bgemm<true,  true, false, true><<<g1, 256>>>(wq, ht, qt, CH, CH, CH, CH,
        0, sHC, sHC, 0, 1.f, q_b, nullptr);
    bgemm<true,  true, false, true><<<g1, 256>>>(wk, ht, kt, CH, CH, CH, CH,
        0, sHC, sHC, 0, 1.f, k_b, nullptr);
    bgemm<false, true, false, true><<<g1, 256>>>(wv, ht, vv, CH, CH, CH, HWSZ,
        0, sHC, sCHW, 0, 1.f, v_b, nullptr);

    // 3) S[i][j] = (1/sqrt(C)) sum_c qt[i][c] kt[j][c]  (M=N=4096, K=512)
    dim3 g2(HWSZ / BN, HWSZ / BM, BATCH);
    const float alpha = 1.f / sqrtf((float)CH);
    bgemm<false, false, false, true><<<g2, 256>>>(qt, kt, at, CH, CH, CH, HWSZ,
        sHC, sHC, sAtt, 0, alpha, nullptr, nullptr);

    // 4) softmax rows (bf16 in/out, fp32 math)
    softmax_kernel<<<BATCH * HWSZ, 256>>>();

    // 5) out[c][i] = x[c][i] + sum_j v[c][j] attn[i][j]  (M=512, N=4096, K=4096)
    dim3 g3(HWSZ / BN, CH / BM, BATCH);
    bgemm<false, false, true, false><<<g3, 256>>>(vv, at, out, HWSZ, HWSZ, HWSZ, HWSZ,
        sCHW, sAtt, sCHW, sCHW, 1.f, nullptr, x);
}